// round 1
// baseline (speedup 1.0000x reference)
#include <cuda_runtime.h>
#include <math.h>

// FilterInterpolationModule: adaptive (4x4) filter + bilinear warp.
// One thread per (b, y, x); computes all C=3 channels.
// The 16 taps x 4 bilinear corners collapse to a 5x5 patch with an
// effective per-pixel 5x5 weight kernel (exact reorder of the reference sum).

namespace {
constexpr int H  = 544;
constexpr int W  = 960;
constexpr int C  = 3;
constexpr int FS = 4;
constexpr int HW = H * W;
}

__global__ __launch_bounds__(256) void filter_interp_kernel(
    const float* __restrict__ input1,   // [B, C, H, W]
    const float* __restrict__ input2,   // [B, 2, H, W]  (fx, fy)
    const float* __restrict__ input3,   // [B, 16, H, W]
    float* __restrict__ out)            // [B, C, H, W]
{
    const int pix = blockIdx.x * blockDim.x + threadIdx.x;
    const int b   = blockIdx.y;
    if (pix >= HW) return;

    const int y = pix / W;
    const int x = pix - y * W;

    const float fx = input2[(b * 2 + 0) * HW + pix];
    const float fy = input2[(b * 2 + 1) * HW + pix];

    const float x2 = (float)x + fx;
    const float y2 = (float)y + fy;

    const bool mask =
        (x2 >= 0.0f) && (y2 >= 0.0f) &&
        (x2 <= (float)(W - 1)) && (y2 <= (float)(H - 1)) &&
        (fabsf(fx) < (float)W * 0.5f) && (fabsf(fy) < (float)H * 0.5f);

    float* outp = out + (size_t)(b * C) * HW + pix;

    if (!mask) {
#pragma unroll
        for (int c = 0; c < C; c++) outp[c * HW] = 0.0f;
        return;
    }

    const float x2c = fminf(fmaxf(x2, 0.0f), (float)(W - 1));
    const float y2c = fminf(fmaxf(y2, 0.0f), (float)(H - 1));
    const int ix = (int)floorf(x2c);
    const int iy = (int)floorf(y2c);
    const float alpha = x2c - (float)ix;
    const float beta  = y2c - (float)iy;
    const int ixL = ix - 1;   // ix + 1 - fs/2
    const int iyT = iy - 1;

    const float wa = (1.0f - alpha) * (1.0f - beta);
    const float wb = alpha * (1.0f - beta);
    const float wc = (1.0f - alpha) * beta;
    const float wd = alpha * beta;

    // Build effective 5x5 weights: eff[j'][i'] = sum of bilinear-weighted
    // contributions of all 4x4 filter taps touching patch position (j', i').
    float eff[5][5];
#pragma unroll
    for (int j = 0; j < 5; j++)
#pragma unroll
        for (int i = 0; i < 5; i++) eff[j][i] = 0.0f;

    const float* w3p = input3 + (size_t)(b * FS * FS) * HW + pix;
#pragma unroll
    for (int j = 0; j < FS; j++) {
#pragma unroll
        for (int i = 0; i < FS; i++) {
            const float w = w3p[(j * FS + i) * HW];
            eff[j][i]         += wa * w;
            eff[j][i + 1]     += wb * w;
            eff[j + 1][i]     += wc * w;
            eff[j + 1][i + 1] += wd * w;
        }
    }

    // Clipped patch indices (matches reference's per-tap clipping exactly).
    int rowOff[5];
    int colIdx[5];
#pragma unroll
    for (int k = 0; k < 5; k++) {
        int r = iyT + k;
        r = min(max(r, 0), H - 1);
        rowOff[k] = r * W;
        int cc = ixL + k;
        cc = min(max(cc, 0), W - 1);
        colIdx[k] = cc;
    }

    const float* img = input1 + (size_t)(b * C) * HW;
#pragma unroll
    for (int c = 0; c < C; c++) {
        const float* imgc = img + c * HW;
        float acc = 0.0f;
#pragma unroll
        for (int j = 0; j < 5; j++) {
#pragma unroll
            for (int i = 0; i < 5; i++) {
                acc += eff[j][i] * __ldg(imgc + rowOff[j] + colIdx[i]);
            }
        }
        outp[c * HW] = acc;
    }
}

extern "C" void kernel_launch(void* const* d_in, const int* in_sizes, int n_in,
                              void* d_out, int out_size) {
    const float* input1 = (const float*)d_in[0];
    const float* input2 = (const float*)d_in[1];
    const float* input3 = (const float*)d_in[2];
    float* out = (float*)d_out;

    const int B = in_sizes[1] / (2 * HW);

    dim3 block(256);
    dim3 grid((HW + 255) / 256, B);
    filter_interp_kernel<<<grid, block>>>(input1, input2, input3, out);
}